// round 17
// baseline (speedup 1.0000x reference)
#include <cuda_runtime.h>

#define GRID_BLOCKS 2048
#define BLOCK_THREADS 256

__device__ float g_sum = 0.0f;
__device__ unsigned int g_done_count = 0;

__global__ __launch_bounds__(BLOCK_THREADS, 8)
void mtnll_fused_kernel(const float* __restrict__ in0,
                        const float* __restrict__ in1,
                        const float* __restrict__ in2,
                        const float4* __restrict__ cmap4,
                        const int4* __restrict__ t0q,
                        const int4* __restrict__ t1q,
                        const int4* __restrict__ t2q,
                        float* __restrict__ out,
                        int n)                    // n = N (rows); N % 4 == 0
{
    float acc = 0.0f;

    // Each index q covers rows {4q..4q+3}. Metadata as 128-bit loads,
    // logit gathers stay scalar (proven fastest pattern).
    const int nq = n >> 2;
    const int stride = gridDim.x * blockDim.x;   // 524288 -> exactly 2 iters
    for (int q = blockIdx.x * blockDim.x + threadIdx.x; q < nq; q += stride) {
        const int4   a4 = __ldg(&t0q[q]);
        const int4   b4 = __ldg(&t1q[q]);
        const int4   c4 = __ldg(&t2q[q]);
        const float4 w4 = __ldg(&cmap4[q]);

        const int r0 = 12 * q;        // row 4q
        const int r1 = 12 * q + 3;    // row 4q+1
        const int r2 = 12 * q + 6;    // row 4q+2
        const int r3 = 12 * q + 9;    // row 4q+3

        const float p00 = __ldg(&in0[r0 + a4.x]);
        const float p01 = __ldg(&in1[r0 + b4.x]);
        const float p02 = __ldg(&in2[r0 + c4.x]);
        const float p10 = __ldg(&in0[r1 + a4.y]);
        const float p11 = __ldg(&in1[r1 + b4.y]);
        const float p12 = __ldg(&in2[r1 + c4.y]);
        const float p20 = __ldg(&in0[r2 + a4.z]);
        const float p21 = __ldg(&in1[r2 + b4.z]);
        const float p22 = __ldg(&in2[r2 + c4.z]);
        const float p30 = __ldg(&in0[r3 + a4.w]);
        const float p31 = __ldg(&in1[r3 + b4.w]);
        const float p32 = __ldg(&in2[r3 + c4.w]);

        const float s0 = fmaf(0.5f, p01, fmaf(0.25f, p02, p00));
        const float s1 = fmaf(0.5f, p11, fmaf(0.25f, p12, p10));
        const float s2 = fmaf(0.5f, p21, fmaf(0.25f, p22, p20));
        const float s3 = fmaf(0.5f, p31, fmaf(0.25f, p32, p30));
        acc = fmaf(-w4.x, s0, acc);
        acc = fmaf(-w4.y, s1, acc);
        acc = fmaf(-w4.z, s2, acc);
        acc = fmaf(-w4.w, s3, acc);
    }

    // intra-block reduction
    #pragma unroll
    for (int o = 16; o > 0; o >>= 1)
        acc += __shfl_xor_sync(0xffffffffu, acc, o);

    __shared__ float smem[BLOCK_THREADS / 32];
    const int warp = threadIdx.x >> 5;
    const int lane = threadIdx.x & 31;
    if (lane == 0) smem[warp] = acc;
    __syncthreads();

    // thread 0: one atomic into a single device scalar, then elect last block
    if (threadIdx.x == 0) {
        float bsum = 0.0f;
        #pragma unroll
        for (int w = 0; w < BLOCK_THREADS / 32; w++) bsum += smem[w];
        atomicAdd(&g_sum, bsum);
        __threadfence();
        unsigned int prev = atomicAdd(&g_done_count, 1u);
        if (prev == gridDim.x - 1) {
            // all blocks' adds are visible (each fenced before bumping the count)
            float total = *((volatile float*)&g_sum);
            out[0] = total * (1.0f / (float)n);
            g_sum = 0.0f;        // reset for next graph replay
            g_done_count = 0;
        }
    }
}

extern "C" void kernel_launch(void* const* d_in, const int* in_sizes, int n_in,
                              void* d_out, int out_size) {
    const float* in0    = (const float*)d_in[0];
    const float* in1    = (const float*)d_in[1];
    const float* in2    = (const float*)d_in[2];
    const float4* cmap4 = (const float4*)d_in[3];
    const int4* t0q     = (const int4*)d_in[4];
    const int4* t1q     = (const int4*)d_in[5];
    const int4* t2q     = (const int4*)d_in[6];
    float* out = (float*)d_out;

    const int n = in_sizes[3];   // N, divisible by 4

    mtnll_fused_kernel<<<GRID_BLOCKS, BLOCK_THREADS>>>(
        in0, in1, in2, cmap4, t0q, t1q, t2q, out, n);
}